// round 1
// baseline (speedup 1.0000x reference)
#include <cuda_runtime.h>

// Involution2d fused kernel for GB300 (sm_103a)
// B=4, C=256, H=W=64, G=16, Cg=16, K=7 (49 taps), PAD=3
//
// One block per (b, h, g): 256 threads.
//  Stage 0: load x[b, :, h, :]      -> smem x_s[c][64]        (64 KB)
//           load w_kernel[g*49.. ]  -> smem w_s[c][65] (k-dim padded to 64, stride 65)
//  Stage 1: kern[p][k] = sum_c x_s[c][p] * w_s[c][k] + bias   (4x4 register fragments)
//  Stage 2: out[b, g*16+cg, h, w] = sum_{kh,kw} x[b,c,h+kh-3,w+kw-3] * kern[w][kh*7+kw]

#define BB 4
#define CH 256
#define HH 64
#define WW 64
#define GG 16
#define CG 16
#define KT 7
#define KK 49          // 7*7 taps
#define KP 64          // padded tap count for fragment math
#define WSTR 65        // w_s row stride (odd -> conflict-free transpose stores)

#define SM_X   (CH * WW)          // 16384 floats
#define SM_W   (CH * WSTR)        // 16640 floats
#define SM_K   (WW * KK)          // 3136 floats
#define SMEM_FLOATS (SM_X + SM_W + SM_K)
#define SMEM_BYTES  (SMEM_FLOATS * 4)

__global__ __launch_bounds__(256, 1)
void involution2d_fused_kernel(const float* __restrict__ x,
                               const float* __restrict__ w_kernel,
                               const float* __restrict__ b_kernel,
                               float* __restrict__ out) {
    extern __shared__ float smem[];
    float* x_s = smem;                 // [c][64]
    float* w_s = smem + SM_X;          // [c][65], taps 0..63 (49..63 zero)
    float* k_s = smem + SM_X + SM_W;   // [p][49]

    const int rb = blockIdx.x;         // b*H + h
    const int b  = rb >> 6;
    const int h  = rb & 63;
    const int g  = blockIdx.y;
    const int t  = threadIdx.x;

    // ---- Stage 0a: load x row slice (all 256 channels, 64 cols), coalesced ----
    const float* xb = x + (size_t)b * CH * HH * WW + h * WW;
    #pragma unroll
    for (int idx = t; idx < CH * WW; idx += 256) {
        const int c = idx >> 6;
        const int w = idx & 63;
        x_s[idx] = xb[c * (HH * WW) + w];
    }

    // ---- Stage 0b: load + transpose w slice for this group ----
    // gmem: w_kernel[(g*49+k)*256 + c]  ->  smem: w_s[c*65 + k]
    // stores stride-65 across lanes -> conflict-free
    const float* wg = w_kernel + g * KK * CH;
    for (int idx = t; idx < KK * CH; idx += 256) {
        const int k = idx >> 8;
        const int c = idx & 255;
        w_s[c * WSTR + k] = wg[idx];
    }
    // zero the padded taps 49..63
    for (int idx = t; idx < (KP - KK) * CH; idx += 256) {
        const int c = idx / (KP - KK);
        const int k = KK + idx % (KP - KK);
        w_s[c * WSTR + k] = 0.0f;
    }
    __syncthreads();

    // ---- Stage 1: kern[p][k] = sum_c x_s[c][p] * w_s[c][k], 4x4 fragments ----
    const int p0 = (t & 15) << 2;      // pixel base:  0,4,...,60
    const int k0 = (t >> 4) << 2;      // tap base:    0,4,...,60 (padded to 64)

    float acc00 = 0.f, acc01 = 0.f, acc02 = 0.f, acc03 = 0.f;
    float acc10 = 0.f, acc11 = 0.f, acc12 = 0.f, acc13 = 0.f;
    float acc20 = 0.f, acc21 = 0.f, acc22 = 0.f, acc23 = 0.f;
    float acc30 = 0.f, acc31 = 0.f, acc32 = 0.f, acc33 = 0.f;

    #pragma unroll 4
    for (int c = 0; c < CH; ++c) {
        const float4 xv = *reinterpret_cast<const float4*>(x_s + c * WW + p0);
        const float* wr = w_s + c * WSTR + k0;
        const float w0 = wr[0];
        const float w1 = wr[1];
        const float w2 = wr[2];
        const float w3 = wr[3];
        acc00 += xv.x * w0; acc01 += xv.x * w1; acc02 += xv.x * w2; acc03 += xv.x * w3;
        acc10 += xv.y * w0; acc11 += xv.y * w1; acc12 += xv.y * w2; acc13 += xv.y * w3;
        acc20 += xv.z * w0; acc21 += xv.z * w1; acc22 += xv.z * w2; acc23 += xv.z * w3;
        acc30 += xv.w * w0; acc31 += xv.w * w1; acc32 += xv.w * w2; acc33 += xv.w * w3;
    }

    // epilogue: add bias, store valid taps to k_s[p*49 + k]
    {
        float accs[4][4] = {{acc00,acc01,acc02,acc03},
                            {acc10,acc11,acc12,acc13},
                            {acc20,acc21,acc22,acc23},
                            {acc30,acc31,acc32,acc33}};
        #pragma unroll
        for (int ki = 0; ki < 4; ++ki) {
            const int k = k0 + ki;
            if (k < KK) {
                const float bias = b_kernel[g * KK + k];
                #pragma unroll
                for (int pi = 0; pi < 4; ++pi) {
                    k_s[(p0 + pi) * KK + k] = accs[pi][ki] + bias;
                }
            }
        }
    }
    __syncthreads();

    // ---- Stage 2: apply 49-tap per-pixel kernel to the group's 16 channels ----
    const int w   = t & 63;            // output column
    const int cg0 = t >> 6;            // 0..3
    const float* ks = k_s + w * KK;    // stride 49 across lanes -> conflict-free

    #pragma unroll
    for (int i = 0; i < 4; ++i) {
        const int cg = cg0 + (i << 2);           // covers 0..15
        const int c  = g * CG + cg;
        const float* xc = x + ((size_t)b * CH + c) * (HH * WW);
        float sum = 0.0f;
        #pragma unroll
        for (int kh = 0; kh < KT; ++kh) {
            const int hh = h + kh - 3;
            if ((unsigned)hh < (unsigned)HH) {
                const float* xr = xc + hh * WW;
                const float* kr = ks + kh * KT;
                #pragma unroll
                for (int kw = 0; kw < KT; ++kw) {
                    const int ww = w + kw - 3;
                    if ((unsigned)ww < (unsigned)WW)
                        sum += xr[ww] * kr[kw];
                }
            }
        }
        out[(((size_t)b * CH + c) * HH + h) * WW + w] = sum;
    }
}

extern "C" void kernel_launch(void* const* d_in, const int* in_sizes, int n_in,
                              void* d_out, int out_size) {
    const float* x  = (const float*)d_in[0];
    const float* wk = (const float*)d_in[1];
    const float* bk = (const float*)d_in[2];
    float* out      = (float*)d_out;

    cudaFuncSetAttribute(involution2d_fused_kernel,
                         cudaFuncAttributeMaxDynamicSharedMemorySize, SMEM_BYTES);

    dim3 grid(BB * HH, GG);   // (256, 16) = 4096 blocks
    involution2d_fused_kernel<<<grid, 256, SMEM_BYTES>>>(x, wk, bk, out);
}

// round 2
// speedup vs baseline: 2.0766x; 2.0766x over previous
#include <cuda_runtime.h>

// Involution2d on GB300 (sm_103a). B=4, C=256, H=W=64, G=16, K=7, PAD=3.
//
// Pre-kernel: transpose w_kernel[784][256] -> g_wt[256][1024]
//             (col = gq*256 + grp*64 + k, taps padded 49->64 with zeros)
// Main kernel: block = (b*64+h, gq), 256 threads, 2 blocks/SM.
//   Stage 1: kern[64px][256 padded taps] = X[64px][256c] * W[256c][256taps]
//            c streamed in 8 chunks of 32, double-buffered cp.async,
//            8x8 register fragments per thread.
//   Stage 2: 49-tap dynamic conv; thread = 4 adjacent px x 4 channels of one
//            group (k values reused 4x from registers), float4 output stores.

#define CH 256
#define HH 64
#define WW 64
#define KT 7
#define KK 49
#define KPAD 64
#define CGQ 4                 // groups per block
#define TAPS 256              // CGQ * KPAD
#define RTAPS 196             // CGQ * KK
#define CC 32                 // channels per chunk
#define NCHUNK 8
#define KSTR 197              // k_s row stride (odd -> conflict-free)
#define WT_STRIDE 1024        // g_wt row stride: 4 quads * 256 padded taps

#define XBUF_F (CC * WW)      // 2048 floats per x buffer
#define WBUF_F (CC * TAPS)    // 8192 floats per w buffer
#define SMEM_FLOATS (2 * XBUF_F + 2 * WBUF_F)   // 20480
#define SMEM_BYTES (SMEM_FLOATS * 4)            // 81920

__device__ float g_wt[CH * WT_STRIDE];          // 1 MB static scratch

// ---------------- w transpose + pad kernel ----------------
__global__ void wt_transpose_kernel(const float* __restrict__ wk) {
    __shared__ float s[32][33];
    const int c0   = blockIdx.x * 32;
    const int col0 = blockIdx.y * 32;
    const int tx = threadIdx.x, ty = threadIdx.y;

    const int col = col0 + ty;
    const int gq  = col >> 8;
    const int rem = col & 255;
    const int grp = rem >> 6;
    const int k   = rem & 63;
    float v = 0.0f;
    if (k < KK) {
        const int r = (gq * 4 + grp) * KK + k;       // row in w_kernel
        v = wk[r * CH + c0 + tx];                    // coalesced read
    }
    s[ty][tx] = v;
    __syncthreads();
    g_wt[(c0 + ty) * WT_STRIDE + col0 + tx] = s[tx][ty];  // coalesced write
}

// ---------------- cp.async helpers ----------------
__device__ __forceinline__ void cp16(float* dst, const float* src) {
    unsigned sa = (unsigned)__cvta_generic_to_shared(dst);
    asm volatile("cp.async.cg.shared.global [%0], [%1], 16;" :: "r"(sa), "l"(src));
}
__device__ __forceinline__ void cp_commit() { asm volatile("cp.async.commit_group;"); }
__device__ __forceinline__ void cp_wait1()  { asm volatile("cp.async.wait_group 1;"); }
__device__ __forceinline__ void cp_wait0()  { asm volatile("cp.async.wait_group 0;"); }

// ---------------- main fused kernel ----------------
__global__ __launch_bounds__(256, 2)
void invo_main_kernel(const float* __restrict__ x,
                      const float* __restrict__ bk,
                      float* __restrict__ out) {
    extern __shared__ float sm[];
    float* xbuf0 = sm;
    float* xbuf1 = sm + XBUF_F;
    float* wbuf0 = sm + 2 * XBUF_F;
    float* wbuf1 = sm + 2 * XBUF_F + WBUF_F;
    float* k_s   = sm;                       // aliases buffers after stage 1

    const int t  = threadIdx.x;
    const int rb = blockIdx.x;
    const int b  = rb >> 6;
    const int h  = rb & 63;
    const int gq = blockIdx.y;

    // ---- chunk loader: x rows c0..c0+31 of row h, and w_t columns for gq ----
    auto load_chunk = [&](int chunk, int pb) {
        const int c0 = chunk * CC;
        float* xb = pb ? xbuf1 : xbuf0;
        float* wb = pb ? wbuf1 : wbuf0;
        #pragma unroll
        for (int u = t; u < XBUF_F / 4; u += 256) {       // 512 units, 2/thread
            const int cc = u >> 4;
            const int w4 = (u & 15) << 2;
            cp16(xb + cc * WW + w4,
                 x + ((size_t)(b * CH + c0 + cc) * HH + h) * WW + w4);
        }
        #pragma unroll
        for (int u = t; u < WBUF_F / 4; u += 256) {       // 2048 units, 8/thread
            const int cc = u >> 6;
            const int t4 = (u & 63) << 2;
            cp16(wb + cc * TAPS + t4,
                 g_wt + (size_t)(c0 + cc) * WT_STRIDE + gq * TAPS + t4);
        }
        cp_commit();
    };

    // ---- Stage 1: 8x8 fragment GEMM over streamed chunks ----
    const int p0  = (t & 7) << 3;    // pixel base 0..56
    const int kq0 = (t >> 3) << 3;   // padded tap base 0..248

    float acc[8][8];
    #pragma unroll
    for (int i = 0; i < 8; ++i)
        #pragma unroll
        for (int j = 0; j < 8; ++j) acc[i][j] = 0.0f;

    load_chunk(0, 0);
    for (int ch = 0; ch < NCHUNK; ++ch) {
        const int pb = ch & 1;
        if (ch + 1 < NCHUNK) { load_chunk(ch + 1, pb ^ 1); cp_wait1(); }
        else                 { cp_wait0(); }
        __syncthreads();

        const float* xb = pb ? xbuf1 : xbuf0;
        const float* wb = pb ? wbuf1 : wbuf0;

        #pragma unroll 2
        for (int cc = 0; cc < CC; ++cc) {
            const float4 xa = *reinterpret_cast<const float4*>(xb + cc * WW + p0);
            const float4 xc = *reinterpret_cast<const float4*>(xb + cc * WW + p0 + 4);
            const float4 wa = *reinterpret_cast<const float4*>(wb + cc * TAPS + kq0);
            const float4 wc = *reinterpret_cast<const float4*>(wb + cc * TAPS + kq0 + 4);
            const float xv[8] = {xa.x, xa.y, xa.z, xa.w, xc.x, xc.y, xc.z, xc.w};
            const float wv[8] = {wa.x, wa.y, wa.z, wa.w, wc.x, wc.y, wc.z, wc.w};
            #pragma unroll
            for (int pi = 0; pi < 8; ++pi)
                #pragma unroll
                for (int ki = 0; ki < 8; ++ki)
                    acc[pi][ki] += xv[pi] * wv[ki];
        }
        __syncthreads();   // guards buffer reuse by next chunk's cp.async
    }

    // ---- epilogue: bias add, write valid taps to k_s (aliases buffers) ----
    {
        const int grp = kq0 >> 6;
        const int kk0 = kq0 & 63;
        #pragma unroll
        for (int ki = 0; ki < 8; ++ki) {
            const int kk = kk0 + ki;
            if (kk < KK) {
                const float bias = bk[(gq * CGQ + grp) * KK + kk];
                #pragma unroll
                for (int pi = 0; pi < 8; ++pi)
                    k_s[(p0 + pi) * KSTR + grp * KK + kk] = acc[pi][ki] + bias;
            }
        }
    }
    __syncthreads();

    // ---- Stage 2: apply per-pixel 7x7 kernels ----
    // thread: 4 adjacent pixels (w0..w0+3) x 4 channels {j, j+4, j+8, j+12} of group grp2
    const int wg   = t & 15;
    const int w0   = wg << 2;
    const int q    = t >> 4;
    const int grp2 = q >> 2;
    const int j    = q & 3;

    float o[4][4];
    #pragma unroll
    for (int m = 0; m < 4; ++m)
        #pragma unroll
        for (int pi = 0; pi < 4; ++pi) o[m][pi] = 0.0f;

    #pragma unroll
    for (int kh = 0; kh < KT; ++kh) {
        const int hh = h + kh - 3;
        if ((unsigned)hh >= (unsigned)HH) continue;

        // per-pixel kernel values for this kh row: reused across 4 channels
        float kv[4][KT];
        #pragma unroll
        for (int pi = 0; pi < 4; ++pi)
            #pragma unroll
            for (int kw = 0; kw < KT; ++kw)
                kv[pi][kw] = k_s[(w0 + pi) * KSTR + grp2 * KK + kh * KT + kw];

        #pragma unroll
        for (int m = 0; m < 4; ++m) {
            const int c = gq * 64 + grp2 * 16 + j + (m << 2);
            const float* xr = x + ((size_t)(b * CH + c) * HH + hh) * WW;
            float xv[10];
            #pragma unroll
            for (int jj = 0; jj < 10; ++jj) {
                const int ww = w0 - 3 + jj;
                xv[jj] = ((unsigned)ww < (unsigned)WW) ? xr[ww] : 0.0f;
            }
            #pragma unroll
            for (int kw = 0; kw < KT; ++kw)
                #pragma unroll
                for (int pi = 0; pi < 4; ++pi)
                    o[m][pi] += xv[pi + kw] * kv[pi][kw];
        }
    }

    #pragma unroll
    for (int m = 0; m < 4; ++m) {
        const int c = gq * 64 + grp2 * 16 + j + (m << 2);
        const float4 r4 = make_float4(o[m][0], o[m][1], o[m][2], o[m][3]);
        *reinterpret_cast<float4*>(out + ((size_t)(b * CH + c) * HH + h) * WW + w0) = r4;
    }
}

extern "C" void kernel_launch(void* const* d_in, const int* in_sizes, int n_in,
                              void* d_out, int out_size) {
    const float* x  = (const float*)d_in[0];
    const float* wk = (const float*)d_in[1];
    const float* bk = (const float*)d_in[2];
    float* out      = (float*)d_out;

    // 1) transpose + pad weights into g_wt
    dim3 tb(32, 32);
    dim3 tg(CH / 32, WT_STRIDE / 32);   // (8, 32)
    wt_transpose_kernel<<<tg, tb>>>(wk);

    // 2) fused involution
    cudaFuncSetAttribute(invo_main_kernel,
                         cudaFuncAttributeMaxDynamicSharedMemorySize, SMEM_BYTES);
    dim3 grid(4 * HH, CGQ);             // (256, 4) = 1024 blocks
    invo_main_kernel<<<grid, 256, SMEM_BYTES>>>(x, bk, out);
}